// round 2
// baseline (speedup 1.0000x reference)
#include <cuda_runtime.h>
#include <cstdint>
#include <cstddef>

#define H 2048
#define NACT 64
#define STEPS 32
#define NLAYERS 2

// ---------------- device state ----------------
__device__ __align__(16) float g_h[2][NLAYERS][H];   // [parity][layer]
__device__ __align__(16) float g_c[NLAYERS][H];
__device__ __align__(16) float g_x[H];
__device__ __align__(16) float g_logits[NACT];
__device__ float g_logp_sum;
__device__ int   g_action;

// ---------------- threefry2x32-20 (bit-exact JAX core) ----------------
__device__ __forceinline__ uint32_t rotl32(uint32_t v, int d) {
    return (v << d) | (v >> (32 - d));
}

__device__ __forceinline__ void threefry2x32(uint32_t k0, uint32_t k1,
                                             uint32_t x0, uint32_t x1,
                                             uint32_t& o0, uint32_t& o1) {
    const uint32_t ks2 = k0 ^ k1 ^ 0x1BD11BDAu;
    x0 += k0; x1 += k1;
    // group 1 (13,15,26,6), inject (k1, ks2+1)
    x0 += x1; x1 = rotl32(x1, 13); x1 ^= x0;
    x0 += x1; x1 = rotl32(x1, 15); x1 ^= x0;
    x0 += x1; x1 = rotl32(x1, 26); x1 ^= x0;
    x0 += x1; x1 = rotl32(x1, 6);  x1 ^= x0;
    x0 += k1; x1 += ks2 + 1u;
    // group 2 (17,29,16,24), inject (ks2, k0+2)
    x0 += x1; x1 = rotl32(x1, 17); x1 ^= x0;
    x0 += x1; x1 = rotl32(x1, 29); x1 ^= x0;
    x0 += x1; x1 = rotl32(x1, 16); x1 ^= x0;
    x0 += x1; x1 = rotl32(x1, 24); x1 ^= x0;
    x0 += ks2; x1 += k0 + 2u;
    // group 3 (13,15,26,6), inject (k0, k1+3)
    x0 += x1; x1 = rotl32(x1, 13); x1 ^= x0;
    x0 += x1; x1 = rotl32(x1, 15); x1 ^= x0;
    x0 += x1; x1 = rotl32(x1, 26); x1 ^= x0;
    x0 += x1; x1 = rotl32(x1, 6);  x1 ^= x0;
    x0 += k0; x1 += k1 + 3u;
    // group 4 (17,29,16,24), inject (k1, ks2+4)
    x0 += x1; x1 = rotl32(x1, 17); x1 ^= x0;
    x0 += x1; x1 = rotl32(x1, 29); x1 ^= x0;
    x0 += x1; x1 = rotl32(x1, 16); x1 ^= x0;
    x0 += x1; x1 = rotl32(x1, 24); x1 ^= x0;
    x0 += k1; x1 += ks2 + 4u;
    // group 5 (13,15,26,6), inject (ks2, k0+5)
    x0 += x1; x1 = rotl32(x1, 13); x1 ^= x0;
    x0 += x1; x1 = rotl32(x1, 15); x1 ^= x0;
    x0 += x1; x1 = rotl32(x1, 26); x1 ^= x0;
    x0 += x1; x1 = rotl32(x1, 6);  x1 ^= x0;
    x0 += ks2; x1 += k0 + 5u;
    o0 = x0; o1 = x1;
}

// JAX uniform(minval=tiny, maxval=1) from raw 32 bits
__device__ __forceinline__ float jax_uniform(uint32_t bits) {
    const float tiny = 1.1754943508222875e-38f;  // finfo(float32).tiny
    uint32_t fb = (bits >> 9) | 0x3f800000u;
    float u = __uint_as_float(fb) - 1.0f;        // [0, 1)
    u = u * 1.0f + tiny;                          // (maxval-minval)==1.0f in fp32
    return fmaxf(tiny, u);
}

// ---------------- init ----------------
__global__ void init_kernel(const float* __restrict__ start_token) {
    int i = blockIdx.x * blockDim.x + threadIdx.x;
    if (i < H) {
        g_x[i] = start_token[i];
        g_c[0][i] = 0.f; g_c[1][i] = 0.f;
        g_h[0][0][i] = 0.f; g_h[0][1][i] = 0.f;
        g_h[1][0][i] = 0.f; g_h[1][1][i] = 0.f;
        if (i == 0) { g_logp_sum = 0.f; g_action = 0; }
    }
}

// ---------------- fused LSTM cell ----------------
// grid = H blocks (one hidden index j each), 256 threads = 8 warps.
// warp w: gate (w&3), matrix (w<4 ? W_ih : W_hh). Thread 0 fuses i/f/g/o.
__global__ void __launch_bounds__(256, 8)
cell_kernel(const float* __restrict__ wih, const float* __restrict__ whh,
            const float* __restrict__ bih, const float* __restrict__ bhh,
            int layer, int t) {
    const int j    = blockIdx.x;
    const int w    = threadIdx.x >> 5;
    const int lane = threadIdx.x & 31;
    const int gate = w & 3;
    const int par_in  = t & 1;
    const int par_out = (t + 1) & 1;

    const float* W = (w < 4) ? wih : whh;
    const float* V;
    if (w < 4) V = (layer == 0) ? g_x : g_h[par_out][0];
    else       V = g_h[par_in][layer];

    const float4* row = reinterpret_cast<const float4*>(W + (size_t)(gate * H + j) * H);
    const float4* v4  = reinterpret_cast<const float4*>(V);

    float s = 0.f;
#pragma unroll 4
    for (int k = lane; k < H / 4; k += 32) {
        float4 a = row[k];
        float4 b = v4[k];
        s = fmaf(a.x, b.x, s);
        s = fmaf(a.y, b.y, s);
        s = fmaf(a.z, b.z, s);
        s = fmaf(a.w, b.w, s);
    }
#pragma unroll
    for (int o = 16; o; o >>= 1) s += __shfl_xor_sync(0xffffffffu, s, o);

    __shared__ float sm[8];
    if (lane == 0) sm[w] = s;
    __syncthreads();

    if (threadIdx.x == 0) {
        float gi = sm[0] + sm[4] + bih[j]         + bhh[j];
        float gf = sm[1] + sm[5] + bih[H + j]     + bhh[H + j];
        float gg = sm[2] + sm[6] + bih[2 * H + j] + bhh[2 * H + j];
        float go = sm[3] + sm[7] + bih[3 * H + j] + bhh[3 * H + j];
        float i_ = 1.0f / (1.0f + expf(-gi));
        float f_ = 1.0f / (1.0f + expf(-gf));
        float g_ = tanhf(gg);
        float o_ = 1.0f / (1.0f + expf(-go));
        float cn = f_ * g_c[layer][j] + i_ * g_;
        g_c[layer][j] = cn;
        g_h[par_out][layer][j] = o_ * tanhf(cn);
    }
}

// ---------------- head matvec: logits = head_w[t] @ h + head_b[t] ----------------
__global__ void head_kernel(const float* __restrict__ hw,
                            const float* __restrict__ hb, int t) {
    const int r    = blockIdx.x;          // 0..63
    const int tid  = threadIdx.x;         // 256 threads
    const int par_out = (t + 1) & 1;
    const float4* row = reinterpret_cast<const float4*>(hw + (size_t)r * H);
    const float4* v4  = reinterpret_cast<const float4*>(g_h[par_out][1]);

    float s = 0.f;
#pragma unroll
    for (int k = tid; k < H / 4; k += 256) {
        float4 a = row[k];
        float4 b = v4[k];
        s = fmaf(a.x, b.x, s);
        s = fmaf(a.y, b.y, s);
        s = fmaf(a.z, b.z, s);
        s = fmaf(a.w, b.w, s);
    }
#pragma unroll
    for (int o = 16; o; o >>= 1) s += __shfl_xor_sync(0xffffffffu, s, o);
    __shared__ float sm[8];
    if ((tid & 31) == 0) sm[tid >> 5] = s;
    __syncthreads();
    if (tid == 0) {
        float tot = sm[0] + sm[1] + sm[2] + sm[3] + sm[4] + sm[5] + sm[6] + sm[7];
        g_logits[r] = tot + hb[r];
    }
}

// ---------------- sample: gumbel-argmax + log_softmax + next embedding ----------------
// RNG follows JAX's *partitionable* threefry (default since jax 0.4.30):
//   split(key(42), 32)[t] = threefry2x32(key, hi=0, lo=t)  -> (kk0, kk1)
//   random_bits(k, 32, (64,))[i] = o0 ^ o1 of threefry2x32(k, hi=0, lo=i)
__global__ void sample_kernel(const float* __restrict__ action_emb,
                              int t, float* __restrict__ out, int out_size) {
    const int tid = threadIdx.x;

    if (tid < 32) {
        const int lane = tid;
        // step subkey (partitionable split): counter = uint64 t -> (hi=0, lo=t)
        uint32_t kk0, kk1;
        threefry2x32(0u, 42u, 0u, (uint32_t)t, kk0, kk1);

        // bits for actions lane and lane+32: counter = uint64 i -> (hi=0, lo=i)
        uint32_t a0, a1, b0, b1;
        threefry2x32(kk0, kk1, 0u, (uint32_t)lane,        a0, a1);
        threefry2x32(kk0, kk1, 0u, (uint32_t)(lane + 32), b0, b1);
        uint32_t bits0 = a0 ^ a1;   // 32-bit fold of the two output words
        uint32_t bits1 = b0 ^ b1;

        float u0 = jax_uniform(bits0);
        float u1 = jax_uniform(bits1);
        float gum0 = -logf(-logf(u0));
        float gum1 = -logf(-logf(u1));

        float l0 = g_logits[lane];
        float l1 = g_logits[lane + 32];
        float v0 = l0 + gum0;
        float v1 = l1 + gum1;

        float bestv; int besti;
        if (v1 > v0) { bestv = v1; besti = lane + 32; }
        else         { bestv = v0; besti = lane; }
#pragma unroll
        for (int o = 16; o; o >>= 1) {
            float ov = __shfl_xor_sync(0xffffffffu, bestv, o);
            int   oi = __shfl_xor_sync(0xffffffffu, besti, o);
            if (ov > bestv || (ov == bestv && oi < besti)) { bestv = ov; besti = oi; }
        }
        // log_softmax denominator
        float m = fmaxf(l0, l1);
#pragma unroll
        for (int o = 16; o; o >>= 1) m = fmaxf(m, __shfl_xor_sync(0xffffffffu, m, o));
        float se = expf(l0 - m) + expf(l1 - m);
#pragma unroll
        for (int o = 16; o; o >>= 1) se += __shfl_xor_sync(0xffffffffu, se, o);

        if (lane == 0) {
            float logp = (g_logits[besti] - m) - logf(se);
            float news = g_logp_sum + logp;
            g_logp_sum = news;
            g_action   = besti;
            out[t] = (float)besti;
            if (t == STEPS - 1 && out_size > STEPS) out[STEPS] = news;
        }
    }
    __syncthreads();
    // next input embedding
    int a = g_action;
    const float* src = action_emb + (size_t)a * H;
    for (int k = tid; k < H; k += 256) g_x[k] = src[k];
}

// ---------------- launch ----------------
extern "C" void kernel_launch(void* const* d_in, const int* in_sizes, int n_in,
                              void* d_out, int out_size) {
    const float* start_token = (const float*)d_in[0];
    const float* action_emb  = (const float*)d_in[1];
    const float* w_ih        = (const float*)d_in[2];
    const float* w_hh        = (const float*)d_in[3];
    const float* b_ih        = (const float*)d_in[4];
    const float* b_hh        = (const float*)d_in[5];
    const float* head_w      = (const float*)d_in[6];
    const float* head_b      = (const float*)d_in[7];
    float* out = (float*)d_out;

    init_kernel<<<(H + 255) / 256, 256>>>(start_token);

    for (int t = 0; t < STEPS; t++) {
        for (int l = 0; l < NLAYERS; l++) {
            cell_kernel<<<H, 256>>>(w_ih + (size_t)l * 4 * H * H,
                                    w_hh + (size_t)l * 4 * H * H,
                                    b_ih + (size_t)l * 4 * H,
                                    b_hh + (size_t)l * 4 * H,
                                    l, t);
        }
        head_kernel<<<NACT, 256>>>(head_w + (size_t)t * NACT * H,
                                   head_b + (size_t)t * NACT, t);
        sample_kernel<<<1, 256>>>(action_emb, t, out, out_size);
    }
}

// round 3
// speedup vs baseline: 1.2489x; 1.2489x over previous
#include <cuda_runtime.h>
#include <cuda_bf16.h>
#include <cstdint>
#include <cstddef>

#define H 2048
#define NACT 64
#define STEPS 32
#define NLAYERS 2

// ---------------- device state ----------------
__device__ __align__(16) float g_h[2][NLAYERS][H];   // [parity][layer]
__device__ __align__(16) float g_c[NLAYERS][H];
__device__ __align__(16) float g_x[H];
__device__ __align__(16) float g_logits[NACT];
__device__ float g_logp_sum;
__device__ int   g_action;
__device__ int   g_done;

// bf16 weight scratch: [layer][which(ih=0,hh=1)][4H][H]
__device__ __align__(16) __nv_bfloat16 g_wbf[(size_t)NLAYERS * 2 * 4 * H * H];

// ---------------- threefry2x32-20 (bit-exact JAX core) ----------------
__device__ __forceinline__ uint32_t rotl32(uint32_t v, int d) {
    return (v << d) | (v >> (32 - d));
}

__device__ __forceinline__ void threefry2x32(uint32_t k0, uint32_t k1,
                                             uint32_t x0, uint32_t x1,
                                             uint32_t& o0, uint32_t& o1) {
    const uint32_t ks2 = k0 ^ k1 ^ 0x1BD11BDAu;
    x0 += k0; x1 += k1;
    x0 += x1; x1 = rotl32(x1, 13); x1 ^= x0;
    x0 += x1; x1 = rotl32(x1, 15); x1 ^= x0;
    x0 += x1; x1 = rotl32(x1, 26); x1 ^= x0;
    x0 += x1; x1 = rotl32(x1, 6);  x1 ^= x0;
    x0 += k1; x1 += ks2 + 1u;
    x0 += x1; x1 = rotl32(x1, 17); x1 ^= x0;
    x0 += x1; x1 = rotl32(x1, 29); x1 ^= x0;
    x0 += x1; x1 = rotl32(x1, 16); x1 ^= x0;
    x0 += x1; x1 = rotl32(x1, 24); x1 ^= x0;
    x0 += ks2; x1 += k0 + 2u;
    x0 += x1; x1 = rotl32(x1, 13); x1 ^= x0;
    x0 += x1; x1 = rotl32(x1, 15); x1 ^= x0;
    x0 += x1; x1 = rotl32(x1, 26); x1 ^= x0;
    x0 += x1; x1 = rotl32(x1, 6);  x1 ^= x0;
    x0 += k0; x1 += k1 + 3u;
    x0 += x1; x1 = rotl32(x1, 17); x1 ^= x0;
    x0 += x1; x1 = rotl32(x1, 29); x1 ^= x0;
    x0 += x1; x1 = rotl32(x1, 16); x1 ^= x0;
    x0 += x1; x1 = rotl32(x1, 24); x1 ^= x0;
    x0 += k1; x1 += ks2 + 4u;
    x0 += x1; x1 = rotl32(x1, 13); x1 ^= x0;
    x0 += x1; x1 = rotl32(x1, 15); x1 ^= x0;
    x0 += x1; x1 = rotl32(x1, 26); x1 ^= x0;
    x0 += x1; x1 = rotl32(x1, 6);  x1 ^= x0;
    x0 += ks2; x1 += k0 + 5u;
    o0 = x0; o1 = x1;
}

__device__ __forceinline__ float jax_uniform(uint32_t bits) {
    const float tiny = 1.1754943508222875e-38f;
    uint32_t fb = (bits >> 9) | 0x3f800000u;
    float u = __uint_as_float(fb) - 1.0f;
    u = u * 1.0f + tiny;
    return fmaxf(tiny, u);
}

// ---------------- weight conversion fp32 -> bf16 ----------------
// 67.1M elements, processed as float4 groups (16.78M groups).
__global__ void convert_kernel(const float* __restrict__ w_ih,
                               const float* __restrict__ w_hh) {
    const size_t MAT = (size_t)4 * H * H;              // 16.78M per matrix
    const size_t N4  = (size_t)NLAYERS * 2 * MAT / 4;  // float4 groups total
    size_t stride = (size_t)gridDim.x * blockDim.x;
    for (size_t g = (size_t)blockIdx.x * blockDim.x + threadIdx.x; g < N4; g += stride) {
        size_t e = g * 4;
        int mat = (int)(e / MAT);          // 0..3 : [layer][which]
        size_t inner = e - (size_t)mat * MAT;
        int layer = mat >> 1, which = mat & 1;
        const float* src = (which ? w_hh : w_ih) + (size_t)layer * MAT + inner;
        float4 v = *reinterpret_cast<const float4*>(src);
        __nv_bfloat162 lo = __floats2bfloat162_rn(v.x, v.y);
        __nv_bfloat162 hi = __floats2bfloat162_rn(v.z, v.w);
        uint2 packed;
        packed.x = *reinterpret_cast<uint32_t*>(&lo);
        packed.y = *reinterpret_cast<uint32_t*>(&hi);
        *reinterpret_cast<uint2*>(&g_wbf[e]) = packed;
    }
}

// ---------------- init ----------------
__global__ void init_kernel(const float* __restrict__ start_token) {
    int i = blockIdx.x * blockDim.x + threadIdx.x;
    if (i < H) {
        g_x[i] = start_token[i];
        g_c[0][i] = 0.f; g_c[1][i] = 0.f;
        g_h[0][0][i] = 0.f; g_h[0][1][i] = 0.f;
        g_h[1][0][i] = 0.f; g_h[1][1][i] = 0.f;
        if (i == 0) { g_logp_sum = 0.f; g_action = 0; g_done = 0; }
    }
}

// ---------------- fused LSTM cell (bf16 weights) ----------------
// grid = H blocks (one hidden index j), 256 threads = 8 warps.
// warp w: gate (w&3), matrix (w<4 ? W_ih : W_hh).
__global__ void __launch_bounds__(256, 8)
cell_kernel(const float* __restrict__ bih, const float* __restrict__ bhh,
            int layer, int t) {
    const int j    = blockIdx.x;
    const int w    = threadIdx.x >> 5;
    const int lane = threadIdx.x & 31;
    const int gate = w & 3;
    const int par_in  = t & 1;
    const int par_out = (t + 1) & 1;
    const int which = (w < 4) ? 0 : 1;

    const float* V;
    if (which == 0) V = (layer == 0) ? g_x : g_h[par_out][0];
    else            V = g_h[par_in][layer];

    const size_t MAT = (size_t)4 * H * H;
    const __nv_bfloat16* row =
        g_wbf + ((size_t)layer * 2 + which) * MAT + (size_t)(gate * H + j) * H;
    const uint4*  row4 = reinterpret_cast<const uint4*>(row);   // 8 bf16 / uint4
    const float4* v4   = reinterpret_cast<const float4*>(V);

    float s = 0.f;
#pragma unroll
    for (int it = 0; it < 8; it++) {
        int k = lane + it * 32;             // uint4 group index, 256 groups total
        uint4 a = row4[k];
        float4 b0 = v4[2 * k];
        float4 b1 = v4[2 * k + 1];
        float2 f0 = __bfloat1622float2(*reinterpret_cast<__nv_bfloat162*>(&a.x));
        float2 f1 = __bfloat1622float2(*reinterpret_cast<__nv_bfloat162*>(&a.y));
        float2 f2 = __bfloat1622float2(*reinterpret_cast<__nv_bfloat162*>(&a.z));
        float2 f3 = __bfloat1622float2(*reinterpret_cast<__nv_bfloat162*>(&a.w));
        s = fmaf(f0.x, b0.x, s); s = fmaf(f0.y, b0.y, s);
        s = fmaf(f1.x, b0.z, s); s = fmaf(f1.y, b0.w, s);
        s = fmaf(f2.x, b1.x, s); s = fmaf(f2.y, b1.y, s);
        s = fmaf(f3.x, b1.z, s); s = fmaf(f3.y, b1.w, s);
    }
#pragma unroll
    for (int o = 16; o; o >>= 1) s += __shfl_xor_sync(0xffffffffu, s, o);

    __shared__ float sm[8];
    if (lane == 0) sm[w] = s;
    __syncthreads();

    if (threadIdx.x == 0) {
        float gi = sm[0] + sm[4] + bih[j]         + bhh[j];
        float gf = sm[1] + sm[5] + bih[H + j]     + bhh[H + j];
        float gg = sm[2] + sm[6] + bih[2 * H + j] + bhh[2 * H + j];
        float go = sm[3] + sm[7] + bih[3 * H + j] + bhh[3 * H + j];
        float i_ = 1.0f / (1.0f + expf(-gi));
        float f_ = 1.0f / (1.0f + expf(-gf));
        float g_ = tanhf(gg);
        float o_ = 1.0f / (1.0f + expf(-go));
        float cn = f_ * g_c[layer][j] + i_ * g_;
        g_c[layer][j] = cn;
        g_h[par_out][layer][j] = o_ * tanhf(cn);
    }
}

// ---------------- fused head + sample ----------------
// grid = 64 blocks; block r computes logit r; last block to finish samples,
// accumulates logp, and loads the next input embedding.
__global__ void __launch_bounds__(256, 8)
head_sample_kernel(const float* __restrict__ hw, const float* __restrict__ hb,
                   const float* __restrict__ action_emb,
                   int t, float* __restrict__ out, int out_size) {
    const int r   = blockIdx.x;
    const int tid = threadIdx.x;
    const int par_out = (t + 1) & 1;

    // ---- logit r ----
    {
        const float4* row = reinterpret_cast<const float4*>(hw + (size_t)r * H);
        const float4* v4  = reinterpret_cast<const float4*>(g_h[par_out][1]);
        float s = 0.f;
#pragma unroll
        for (int k = tid; k < H / 4; k += 256) {
            float4 a = row[k];
            float4 b = v4[k];
            s = fmaf(a.x, b.x, s);
            s = fmaf(a.y, b.y, s);
            s = fmaf(a.z, b.z, s);
            s = fmaf(a.w, b.w, s);
        }
#pragma unroll
        for (int o = 16; o; o >>= 1) s += __shfl_xor_sync(0xffffffffu, s, o);
        __shared__ float sm[8];
        if ((tid & 31) == 0) sm[tid >> 5] = s;
        __syncthreads();
        if (tid == 0) {
            float tot = sm[0] + sm[1] + sm[2] + sm[3] + sm[4] + sm[5] + sm[6] + sm[7];
            g_logits[r] = tot + hb[r];
        }
    }

    // ---- last-block election ----
    __shared__ int s_last;
    if (tid == 0) {
        __threadfence();
        int old = atomicAdd(&g_done, 1);
        s_last = (old == NACT - 1) ? 1 : 0;
        if (s_last) g_done = 0;             // reset for next step's kernel
    }
    __syncthreads();
    if (!s_last) return;
    __threadfence();                        // acquire: see all g_logits writes

    // ---- sample (partitionable threefry, bit-exact) ----
    if (tid < 32) {
        const int lane = tid;
        uint32_t kk0, kk1;
        threefry2x32(0u, 42u, 0u, (uint32_t)t, kk0, kk1);

        uint32_t a0, a1, b0, b1;
        threefry2x32(kk0, kk1, 0u, (uint32_t)lane,        a0, a1);
        threefry2x32(kk0, kk1, 0u, (uint32_t)(lane + 32), b0, b1);
        float u0 = jax_uniform(a0 ^ a1);
        float u1 = jax_uniform(b0 ^ b1);
        float gum0 = -logf(-logf(u0));
        float gum1 = -logf(-logf(u1));

        float l0 = g_logits[lane];
        float l1 = g_logits[lane + 32];
        float v0 = l0 + gum0;
        float v1 = l1 + gum1;

        float bestv; int besti;
        if (v1 > v0) { bestv = v1; besti = lane + 32; }
        else         { bestv = v0; besti = lane; }
#pragma unroll
        for (int o = 16; o; o >>= 1) {
            float ov = __shfl_xor_sync(0xffffffffu, bestv, o);
            int   oi = __shfl_xor_sync(0xffffffffu, besti, o);
            if (ov > bestv || (ov == bestv && oi < besti)) { bestv = ov; besti = oi; }
        }
        float m = fmaxf(l0, l1);
#pragma unroll
        for (int o = 16; o; o >>= 1) m = fmaxf(m, __shfl_xor_sync(0xffffffffu, m, o));
        float se = expf(l0 - m) + expf(l1 - m);
#pragma unroll
        for (int o = 16; o; o >>= 1) se += __shfl_xor_sync(0xffffffffu, se, o);

        if (lane == 0) {
            float logp = (g_logits[besti] - m) - logf(se);
            float news = g_logp_sum + logp;
            g_logp_sum = news;
            g_action   = besti;
            out[t] = (float)besti;
            if (t == STEPS - 1 && out_size > STEPS) out[STEPS] = news;
        }
    }
    __syncthreads();
    int a = g_action;
    const float* src = action_emb + (size_t)a * H;
    for (int k = tid; k < H; k += 256) g_x[k] = src[k];
}

// ---------------- launch ----------------
extern "C" void kernel_launch(void* const* d_in, const int* in_sizes, int n_in,
                              void* d_out, int out_size) {
    const float* start_token = (const float*)d_in[0];
    const float* action_emb  = (const float*)d_in[1];
    const float* w_ih        = (const float*)d_in[2];
    const float* w_hh        = (const float*)d_in[3];
    const float* b_ih        = (const float*)d_in[4];
    const float* b_hh        = (const float*)d_in[5];
    const float* head_w      = (const float*)d_in[6];
    const float* head_b      = (const float*)d_in[7];
    float* out = (float*)d_out;

    convert_kernel<<<4096, 256>>>(w_ih, w_hh);
    init_kernel<<<(H + 255) / 256, 256>>>(start_token);

    for (int t = 0; t < STEPS; t++) {
        for (int l = 0; l < NLAYERS; l++) {
            cell_kernel<<<H, 256>>>(b_ih + (size_t)l * 4 * H,
                                    b_hh + (size_t)l * 4 * H,
                                    l, t);
        }
        head_sample_kernel<<<NACT, 256>>>(head_w + (size_t)t * NACT * H,
                                          head_b + (size_t)t * NACT,
                                          action_emb, t, out, out_size);
    }
}

// round 4
// speedup vs baseline: 1.2830x; 1.0273x over previous
#include <cuda_runtime.h>
#include <cuda_bf16.h>
#include <cstdint>
#include <cstddef>

#define H 2048
#define NACT 64
#define STEPS 32
#define NLAYERS 2

// ---------------- device state ----------------
__device__ __align__(16) float g_h[2][NLAYERS][H];   // [parity][layer]
__device__ __align__(16) float g_c[NLAYERS][H];
__device__ __align__(16) float g_x[H];
__device__ __align__(16) float g_part[2][NACT];      // head partial dots
__device__ float g_logp_sum;
__device__ int   g_action;
__device__ int   g_done;

// bf16 weight scratch: [layer][which(ih=0,hh=1)][4H][H]
__device__ __align__(16) __nv_bfloat16 g_wbf[(size_t)NLAYERS * 2 * 4 * H * H];

// ---------------- threefry2x32-20 (bit-exact JAX core) ----------------
__device__ __forceinline__ uint32_t rotl32(uint32_t v, int d) {
    return (v << d) | (v >> (32 - d));
}

__device__ __forceinline__ void threefry2x32(uint32_t k0, uint32_t k1,
                                             uint32_t x0, uint32_t x1,
                                             uint32_t& o0, uint32_t& o1) {
    const uint32_t ks2 = k0 ^ k1 ^ 0x1BD11BDAu;
    x0 += k0; x1 += k1;
    x0 += x1; x1 = rotl32(x1, 13); x1 ^= x0;
    x0 += x1; x1 = rotl32(x1, 15); x1 ^= x0;
    x0 += x1; x1 = rotl32(x1, 26); x1 ^= x0;
    x0 += x1; x1 = rotl32(x1, 6);  x1 ^= x0;
    x0 += k1; x1 += ks2 + 1u;
    x0 += x1; x1 = rotl32(x1, 17); x1 ^= x0;
    x0 += x1; x1 = rotl32(x1, 29); x1 ^= x0;
    x0 += x1; x1 = rotl32(x1, 16); x1 ^= x0;
    x0 += x1; x1 = rotl32(x1, 24); x1 ^= x0;
    x0 += ks2; x1 += k0 + 2u;
    x0 += x1; x1 = rotl32(x1, 13); x1 ^= x0;
    x0 += x1; x1 = rotl32(x1, 15); x1 ^= x0;
    x0 += x1; x1 = rotl32(x1, 26); x1 ^= x0;
    x0 += x1; x1 = rotl32(x1, 6);  x1 ^= x0;
    x0 += k0; x1 += k1 + 3u;
    x0 += x1; x1 = rotl32(x1, 17); x1 ^= x0;
    x0 += x1; x1 = rotl32(x1, 29); x1 ^= x0;
    x0 += x1; x1 = rotl32(x1, 16); x1 ^= x0;
    x0 += x1; x1 = rotl32(x1, 24); x1 ^= x0;
    x0 += k1; x1 += ks2 + 4u;
    x0 += x1; x1 = rotl32(x1, 13); x1 ^= x0;
    x0 += x1; x1 = rotl32(x1, 15); x1 ^= x0;
    x0 += x1; x1 = rotl32(x1, 26); x1 ^= x0;
    x0 += x1; x1 = rotl32(x1, 6);  x1 ^= x0;
    x0 += ks2; x1 += k0 + 5u;
    o0 = x0; o1 = x1;
}

__device__ __forceinline__ float jax_uniform(uint32_t bits) {
    const float tiny = 1.1754943508222875e-38f;
    uint32_t fb = (bits >> 9) | 0x3f800000u;
    float u = __uint_as_float(fb) - 1.0f;
    u = u * 1.0f + tiny;
    return fmaxf(tiny, u);
}

// ---------------- weight conversion fp32 -> bf16 ----------------
__global__ void convert_kernel(const float* __restrict__ w_ih,
                               const float* __restrict__ w_hh) {
    const size_t MAT = (size_t)4 * H * H;
    const size_t N4  = (size_t)NLAYERS * 2 * MAT / 4;
    size_t stride = (size_t)gridDim.x * blockDim.x;
    for (size_t g = (size_t)blockIdx.x * blockDim.x + threadIdx.x; g < N4; g += stride) {
        size_t e = g * 4;
        int mat = (int)(e / MAT);
        size_t inner = e - (size_t)mat * MAT;
        int layer = mat >> 1, which = mat & 1;
        const float* src = (which ? w_hh : w_ih) + (size_t)layer * MAT + inner;
        float4 v = *reinterpret_cast<const float4*>(src);
        __nv_bfloat162 lo = __floats2bfloat162_rn(v.x, v.y);
        __nv_bfloat162 hi = __floats2bfloat162_rn(v.z, v.w);
        uint2 packed;
        packed.x = *reinterpret_cast<uint32_t*>(&lo);
        packed.y = *reinterpret_cast<uint32_t*>(&hi);
        *reinterpret_cast<uint2*>(&g_wbf[e]) = packed;
    }
}

// ---------------- init ----------------
__global__ void init_kernel(const float* __restrict__ start_token) {
    int i = blockIdx.x * blockDim.x + threadIdx.x;
    if (i < H) {
        g_x[i] = start_token[i];
        g_c[0][i] = 0.f; g_c[1][i] = 0.f;
        g_h[0][0][i] = 0.f; g_h[0][1][i] = 0.f;
        g_h[1][0][i] = 0.f; g_h[1][1][i] = 0.f;
        if (i == 0) { g_logp_sum = 0.f; g_action = 0; g_done = 0; }
    }
}

// ---------------- fused LSTM cell (bf16 weights, depth-4 prefetch) ----------------
// grid = H blocks (one hidden index j), 256 threads = 8 warps.
// warp w: gate (w&3), matrix (w<4 ? W_ih : W_hh).
__global__ void __launch_bounds__(256)
cell_kernel(const float* __restrict__ bih, const float* __restrict__ bhh,
            int layer, int t) {
    const int j    = blockIdx.x;
    const int w    = threadIdx.x >> 5;
    const int lane = threadIdx.x & 31;
    const int gate = w & 3;
    const int par_in  = t & 1;
    const int par_out = (t + 1) & 1;
    const int which = (w < 4) ? 0 : 1;

    const float* V;
    if (which == 0) V = (layer == 0) ? g_x : g_h[par_out][0];
    else            V = g_h[par_in][layer];

    const size_t MAT = (size_t)4 * H * H;
    const __nv_bfloat16* row =
        g_wbf + ((size_t)layer * 2 + which) * MAT + (size_t)(gate * H + j) * H;
    const uint4*  row4 = reinterpret_cast<const uint4*>(row);   // 256 groups of 8 bf16
    const float4* v4   = reinterpret_cast<const float4*>(V);

    float s0 = 0.f, s1 = 0.f, s2 = 0.f, s3 = 0.f;

    // depth-4 prefetch of the DRAM row stream
    uint4 a0 = row4[lane];
    uint4 a1 = row4[lane + 32];
    uint4 a2 = row4[lane + 64];
    uint4 a3 = row4[lane + 96];

#define CELL_STEP(A, BASE)                                                   \
    {                                                                        \
        float4 b0 = v4[2 * (lane + (BASE))];                                 \
        float4 b1 = v4[2 * (lane + (BASE)) + 1];                             \
        float2 f0 = __bfloat1622float2(*reinterpret_cast<__nv_bfloat162*>(&A.x)); \
        float2 f1 = __bfloat1622float2(*reinterpret_cast<__nv_bfloat162*>(&A.y)); \
        float2 f2 = __bfloat1622float2(*reinterpret_cast<__nv_bfloat162*>(&A.z)); \
        float2 f3 = __bfloat1622float2(*reinterpret_cast<__nv_bfloat162*>(&A.w)); \
        s0 = fmaf(f0.x, b0.x, s0); s0 = fmaf(f0.y, b0.y, s0);                \
        s1 = fmaf(f1.x, b0.z, s1); s1 = fmaf(f1.y, b0.w, s1);                \
        s2 = fmaf(f2.x, b1.x, s2); s2 = fmaf(f2.y, b1.y, s2);                \
        s3 = fmaf(f3.x, b1.z, s3); s3 = fmaf(f3.y, b1.w, s3);                \
    }

    CELL_STEP(a0, 0);   a0 = row4[lane + 128];
    CELL_STEP(a1, 32);  a1 = row4[lane + 160];
    CELL_STEP(a2, 64);  a2 = row4[lane + 192];
    CELL_STEP(a3, 96);  a3 = row4[lane + 224];
    CELL_STEP(a0, 128);
    CELL_STEP(a1, 160);
    CELL_STEP(a2, 192);
    CELL_STEP(a3, 224);
#undef CELL_STEP

    float s = (s0 + s1) + (s2 + s3);
#pragma unroll
    for (int o = 16; o; o >>= 1) s += __shfl_xor_sync(0xffffffffu, s, o);

    __shared__ float sm[8];
    if (lane == 0) sm[w] = s;
    __syncthreads();

    if (threadIdx.x == 0) {
        float gi = sm[0] + sm[4] + bih[j]         + bhh[j];
        float gf = sm[1] + sm[5] + bih[H + j]     + bhh[H + j];
        float gg = sm[2] + sm[6] + bih[2 * H + j] + bhh[2 * H + j];
        float go = sm[3] + sm[7] + bih[3 * H + j] + bhh[3 * H + j];
        float i_ = 1.0f / (1.0f + expf(-gi));
        float f_ = 1.0f / (1.0f + expf(-gf));
        float g_ = tanhf(gg);
        float o_ = 1.0f / (1.0f + expf(-go));
        float cn = f_ * g_c[layer][j] + i_ * g_;
        g_c[layer][j] = cn;
        g_h[par_out][layer][j] = o_ * tanhf(cn);
    }
}

// ---------------- fused head + sample ----------------
// grid = 128 blocks: block bid computes half (bid>>6) of row (bid&63).
// Last block to finish combines partials, samples, loads next embedding.
__global__ void __launch_bounds__(256)
head_sample_kernel(const float* __restrict__ hw, const float* __restrict__ hb,
                   const float* __restrict__ action_emb,
                   int t, float* __restrict__ out, int out_size) {
    const int r    = blockIdx.x & (NACT - 1);
    const int half = blockIdx.x >> 6;
    const int tid  = threadIdx.x;
    const int par_out = (t + 1) & 1;

    // ---- partial dot: 256 float4 = 1024 elements ----
    {
        const float4* row = reinterpret_cast<const float4*>(hw + (size_t)r * H);
        const float4* v4  = reinterpret_cast<const float4*>(g_h[par_out][1]);
        int k = half * 256 + tid;           // one float4 per thread
        float4 a = row[k];
        float4 b = v4[k];
        float s = a.x * b.x + a.y * b.y + a.z * b.z + a.w * b.w;
#pragma unroll
        for (int o = 16; o; o >>= 1) s += __shfl_xor_sync(0xffffffffu, s, o);
        __shared__ float sm[8];
        if ((tid & 31) == 0) sm[tid >> 5] = s;
        __syncthreads();
        if (tid == 0) {
            g_part[half][r] = sm[0] + sm[1] + sm[2] + sm[3]
                            + sm[4] + sm[5] + sm[6] + sm[7];
        }
    }

    // ---- last-block election (128 blocks) ----
    __shared__ int s_last;
    if (tid == 0) {
        __threadfence();
        int old = atomicAdd(&g_done, 1);
        s_last = (old == 2 * NACT - 1) ? 1 : 0;
        if (s_last) g_done = 0;
    }
    __syncthreads();
    if (!s_last) return;
    __threadfence();                        // acquire all g_part writes

    // ---- sample (partitionable threefry, bit-exact) ----
    __shared__ float sl[NACT];
    if (tid < 32) {
        const int lane = tid;
        float l0 = g_part[0][lane]      + g_part[1][lane]      + hb[lane];
        float l1 = g_part[0][lane + 32] + g_part[1][lane + 32] + hb[lane + 32];
        sl[lane] = l0;
        sl[lane + 32] = l1;

        uint32_t kk0, kk1;
        threefry2x32(0u, 42u, 0u, (uint32_t)t, kk0, kk1);
        uint32_t a0, a1, b0, b1;
        threefry2x32(kk0, kk1, 0u, (uint32_t)lane,        a0, a1);
        threefry2x32(kk0, kk1, 0u, (uint32_t)(lane + 32), b0, b1);
        float u0 = jax_uniform(a0 ^ a1);
        float u1 = jax_uniform(b0 ^ b1);
        float gum0 = -logf(-logf(u0));
        float gum1 = -logf(-logf(u1));

        float v0 = l0 + gum0;
        float v1 = l1 + gum1;

        float bestv; int besti;
        if (v1 > v0) { bestv = v1; besti = lane + 32; }
        else         { bestv = v0; besti = lane; }
#pragma unroll
        for (int o = 16; o; o >>= 1) {
            float ov = __shfl_xor_sync(0xffffffffu, bestv, o);
            int   oi = __shfl_xor_sync(0xffffffffu, besti, o);
            if (ov > bestv || (ov == bestv && oi < besti)) { bestv = ov; besti = oi; }
        }
        float m = fmaxf(l0, l1);
#pragma unroll
        for (int o = 16; o; o >>= 1) m = fmaxf(m, __shfl_xor_sync(0xffffffffu, m, o));
        float se = expf(l0 - m) + expf(l1 - m);
#pragma unroll
        for (int o = 16; o; o >>= 1) se += __shfl_xor_sync(0xffffffffu, se, o);

        if (lane == 0) {
            float logp = (sl[besti] - m) - logf(se);
            float news = g_logp_sum + logp;
            g_logp_sum = news;
            g_action   = besti;
            out[t] = (float)besti;
            if (t == STEPS - 1 && out_size > STEPS) out[STEPS] = news;
        }
    }
    __syncthreads();
    int a = g_action;
    const float* src = action_emb + (size_t)a * H;
    for (int k = tid; k < H; k += 256) g_x[k] = src[k];
}

// ---------------- launch ----------------
extern "C" void kernel_launch(void* const* d_in, const int* in_sizes, int n_in,
                              void* d_out, int out_size) {
    const float* start_token = (const float*)d_in[0];
    const float* action_emb  = (const float*)d_in[1];
    const float* w_ih        = (const float*)d_in[2];
    const float* w_hh        = (const float*)d_in[3];
    const float* b_ih        = (const float*)d_in[4];
    const float* b_hh        = (const float*)d_in[5];
    const float* head_w      = (const float*)d_in[6];
    const float* head_b      = (const float*)d_in[7];
    float* out = (float*)d_out;

    convert_kernel<<<4096, 256>>>(w_ih, w_hh);
    init_kernel<<<(H + 255) / 256, 256>>>(start_token);

    for (int t = 0; t < STEPS; t++) {
        for (int l = 0; l < NLAYERS; l++) {
            cell_kernel<<<H, 256>>>(b_ih + (size_t)l * 4 * H,
                                    b_hh + (size_t)l * 4 * H,
                                    l, t);
        }
        head_sample_kernel<<<2 * NACT, 256>>>(head_w + (size_t)t * NACT * H,
                                              head_b + (size_t)t * NACT,
                                              action_emb, t, out, out_size);
    }
}

// round 6
// speedup vs baseline: 1.3067x; 1.0185x over previous
#include <cuda_runtime.h>
#include <cuda_bf16.h>
#include <cstdint>
#include <cstddef>

#define H 2048
#define NACT 64
#define STEPS 32
#define NLAYERS 2

// ---------------- device state ----------------
__device__ __align__(16) float g_h[2][NLAYERS][H];   // [parity][layer]
__device__ __align__(16) float g_c[NLAYERS][H];
__device__ __align__(16) float g_x[H];
__device__ __align__(16) float g_part[2][NACT];      // head partial dots
__device__ float g_logp_sum;
__device__ int   g_action;
__device__ int   g_done;

// bf16 weight scratch: [layer][which][row][permuted 2048 elems]
// Within each row, uint4 group (it*32+l) holds src float4s (64*it+l) and (64*it+32+l).
__device__ __align__(16) __nv_bfloat16 g_wbf[(size_t)NLAYERS * 2 * 4 * H * H];

// ---------------- threefry2x32-20 (bit-exact JAX core) ----------------
__device__ __forceinline__ uint32_t rotl32(uint32_t v, int d) {
    return (v << d) | (v >> (32 - d));
}

__device__ __forceinline__ void threefry2x32(uint32_t k0, uint32_t k1,
                                             uint32_t x0, uint32_t x1,
                                             uint32_t& o0, uint32_t& o1) {
    const uint32_t ks2 = k0 ^ k1 ^ 0x1BD11BDAu;
    x0 += k0; x1 += k1;
    x0 += x1; x1 = rotl32(x1, 13); x1 ^= x0;
    x0 += x1; x1 = rotl32(x1, 15); x1 ^= x0;
    x0 += x1; x1 = rotl32(x1, 26); x1 ^= x0;
    x0 += x1; x1 = rotl32(x1, 6);  x1 ^= x0;
    x0 += k1; x1 += ks2 + 1u;
    x0 += x1; x1 = rotl32(x1, 17); x1 ^= x0;
    x0 += x1; x1 = rotl32(x1, 29); x1 ^= x0;
    x0 += x1; x1 = rotl32(x1, 16); x1 ^= x0;
    x0 += x1; x1 = rotl32(x1, 24); x1 ^= x0;
    x0 += ks2; x1 += k0 + 2u;
    x0 += x1; x1 = rotl32(x1, 13); x1 ^= x0;
    x0 += x1; x1 = rotl32(x1, 15); x1 ^= x0;
    x0 += x1; x1 = rotl32(x1, 26); x1 ^= x0;
    x0 += x1; x1 = rotl32(x1, 6);  x1 ^= x0;
    x0 += k0; x1 += k1 + 3u;
    x0 += x1; x1 = rotl32(x1, 17); x1 ^= x0;
    x0 += x1; x1 = rotl32(x1, 29); x1 ^= x0;
    x0 += x1; x1 = rotl32(x1, 16); x1 ^= x0;
    x0 += x1; x1 = rotl32(x1, 24); x1 ^= x0;
    x0 += k1; x1 += ks2 + 4u;
    x0 += x1; x1 = rotl32(x1, 13); x1 ^= x0;
    x0 += x1; x1 = rotl32(x1, 15); x1 ^= x0;
    x0 += x1; x1 = rotl32(x1, 26); x1 ^= x0;
    x0 += x1; x1 = rotl32(x1, 6);  x1 ^= x0;
    x0 += ks2; x1 += k0 + 5u;
    o0 = x0; o1 = x1;
}

__device__ __forceinline__ float jax_uniform(uint32_t bits) {
    const float tiny = 1.1754943508222875e-38f;
    uint32_t fb = (bits >> 9) | 0x3f800000u;
    float u = __uint_as_float(fb) - 1.0f;
    u = u * 1.0f + tiny;
    return fmaxf(tiny, u);
}

// ---------------- weight conversion fp32 -> bf16 (permuted layout) ----------------
// Output uint4 o: row = o>>8 (32768 rows of 2048 elems), g = o&255, it=g>>5, l=g&31.
// Contains bf16 of src float4s at row-local indices (64*it+l) and (64*it+32+l).
__global__ void convert_kernel(const float* __restrict__ w_ih,
                               const float* __restrict__ w_hh) {
    const size_t MAT  = (size_t)4 * H * H;           // elems per matrix
    const size_t NOUT = (size_t)NLAYERS * 2 * MAT / 8;  // uint4 outputs
    size_t stride = (size_t)gridDim.x * blockDim.x;
    for (size_t o = (size_t)blockIdx.x * blockDim.x + threadIdx.x; o < NOUT; o += stride) {
        size_t rrow = o >> 8;                 // global row id
        int g  = (int)(o & 255);
        int it = g >> 5, l = g & 31;
        int mat = (int)(rrow >> 13);          // 8192 rows per matrix
        size_t rloc = rrow & 8191;
        int layer = mat >> 1, which = mat & 1;
        const float4* s4 = reinterpret_cast<const float4*>(
            (which ? w_hh : w_ih) + (size_t)layer * MAT + rloc * H);
        int p = 64 * it + l;
        float4 sp = s4[p];
        float4 sq = s4[p + 32];
        __nv_bfloat162 c0 = __floats2bfloat162_rn(sp.x, sp.y);
        __nv_bfloat162 c1 = __floats2bfloat162_rn(sp.z, sp.w);
        __nv_bfloat162 c2 = __floats2bfloat162_rn(sq.x, sq.y);
        __nv_bfloat162 c3 = __floats2bfloat162_rn(sq.z, sq.w);
        uint4 packed;
        packed.x = *reinterpret_cast<uint32_t*>(&c0);
        packed.y = *reinterpret_cast<uint32_t*>(&c1);
        packed.z = *reinterpret_cast<uint32_t*>(&c2);
        packed.w = *reinterpret_cast<uint32_t*>(&c3);
        reinterpret_cast<uint4*>(g_wbf)[o] = packed;
    }
}

// ---------------- init ----------------
__global__ void init_kernel(const float* __restrict__ start_token) {
    int i = blockIdx.x * blockDim.x + threadIdx.x;
    if (i < H) {
        g_x[i] = start_token[i];
        g_c[0][i] = 0.f; g_c[1][i] = 0.f;
        g_h[0][0][i] = 0.f; g_h[0][1][i] = 0.f;
        g_h[1][0][i] = 0.f; g_h[1][1][i] = 0.f;
        if (i == 0) { g_logp_sum = 0.f; g_action = 0; g_done = 0; }
    }
}

// ---------------- fused LSTM cell ----------------
// grid = H blocks (hidden index j), 256 threads = 8 warps.
// warp w: gate (w&3), matrix which=(w>>2). Weights: 8 batched LDG.128/lane.
// Vectors staged in smem, consumed via conflict-free LDS.128.
__global__ void __launch_bounds__(256, 4)
cell_kernel(const float* __restrict__ bih, const float* __restrict__ bhh,
            int layer, int t) {
    const int tid  = threadIdx.x;
    const int j    = blockIdx.x;
    const int w    = tid >> 5;
    const int lane = tid & 31;
    const int gate = w & 3;
    const int which = w >> 2;
    const int par_in  = t & 1;
    const int par_out = (t + 1) & 1;

    const size_t MAT = (size_t)4 * H * H;
    const uint4* row4 = reinterpret_cast<const uint4*>(
        g_wbf + ((size_t)layer * 2 + which) * MAT + (size_t)(gate * H + j) * H);

    // batched weight load: 8 independent LDG.128 per lane
    uint4 a[8];
#pragma unroll
    for (int it = 0; it < 8; it++) a[it] = row4[it * 32 + lane];

    // stage both vectors into smem while weight loads are in flight
    __shared__ float4 sv[2][512];
    {
        const float4* v0 = reinterpret_cast<const float4*>(
            (layer == 0) ? g_x : g_h[par_out][0]);
        const float4* v1 = reinterpret_cast<const float4*>(g_h[par_in][layer]);
        sv[0][tid]       = v0[tid];
        sv[0][tid + 256] = v0[tid + 256];
        sv[1][tid]       = v1[tid];
        sv[1][tid + 256] = v1[tid + 256];
    }
    __syncthreads();

    const float4* svv = sv[which];
    float s0 = 0.f, s1 = 0.f, s2 = 0.f, s3 = 0.f;
#pragma unroll
    for (int it = 0; it < 8; it++) {
        float4 b0 = svv[64 * it + lane];        // conflict-free LDS.128
        float4 b1 = svv[64 * it + 32 + lane];
        float2 f0 = __bfloat1622float2(*reinterpret_cast<__nv_bfloat162*>(&a[it].x));
        float2 f1 = __bfloat1622float2(*reinterpret_cast<__nv_bfloat162*>(&a[it].y));
        float2 f2 = __bfloat1622float2(*reinterpret_cast<__nv_bfloat162*>(&a[it].z));
        float2 f3 = __bfloat1622float2(*reinterpret_cast<__nv_bfloat162*>(&a[it].w));
        s0 = fmaf(f0.x, b0.x, s0); s0 = fmaf(f0.y, b0.y, s0);
        s1 = fmaf(f1.x, b0.z, s1); s1 = fmaf(f1.y, b0.w, s1);
        s2 = fmaf(f2.x, b1.x, s2); s2 = fmaf(f2.y, b1.y, s2);
        s3 = fmaf(f3.x, b1.z, s3); s3 = fmaf(f3.y, b1.w, s3);
    }

    float s = (s0 + s1) + (s2 + s3);
#pragma unroll
    for (int o = 16; o; o >>= 1) s += __shfl_xor_sync(0xffffffffu, s, o);

    __shared__ float sm[8];
    if (lane == 0) sm[w] = s;
    __syncthreads();

    if (tid == 0) {
        float gi = sm[0] + sm[4] + bih[j]         + bhh[j];
        float gf = sm[1] + sm[5] + bih[H + j]     + bhh[H + j];
        float gg = sm[2] + sm[6] + bih[2 * H + j] + bhh[2 * H + j];
        float go = sm[3] + sm[7] + bih[3 * H + j] + bhh[3 * H + j];
        float i_ = 1.0f / (1.0f + expf(-gi));
        float f_ = 1.0f / (1.0f + expf(-gf));
        float g_ = tanhf(gg);
        float o_ = 1.0f / (1.0f + expf(-go));
        float cn = f_ * g_c[layer][j] + i_ * g_;
        g_c[layer][j] = cn;
        g_h[par_out][layer][j] = o_ * tanhf(cn);
    }
}

// ---------------- fused head + sample ----------------
// grid = 128 blocks: block bid computes half (bid>>6) of row (bid&63).
// Last block to finish combines partials, samples, loads next embedding.
__global__ void __launch_bounds__(256)
head_sample_kernel(const float* __restrict__ hw, const float* __restrict__ hb,
                   const float* __restrict__ action_emb,
                   int t, float* __restrict__ out, int out_size) {
    const int r    = blockIdx.x & (NACT - 1);
    const int half = blockIdx.x >> 6;
    const int tid  = threadIdx.x;
    const int par_out = (t + 1) & 1;

    {
        const float4* row = reinterpret_cast<const float4*>(hw + (size_t)r * H);
        const float4* v4  = reinterpret_cast<const float4*>(g_h[par_out][1]);
        int k = half * 256 + tid;
        float4 a = row[k];
        float4 b = v4[k];
        float s = a.x * b.x + a.y * b.y + a.z * b.z + a.w * b.w;
#pragma unroll
        for (int o = 16; o; o >>= 1) s += __shfl_xor_sync(0xffffffffu, s, o);
        __shared__ float sm[8];
        if ((tid & 31) == 0) sm[tid >> 5] = s;
        __syncthreads();
        if (tid == 0) {
            g_part[half][r] = sm[0] + sm[1] + sm[2] + sm[3]
                            + sm[4] + sm[5] + sm[6] + sm[7];
        }
    }

    __shared__ int s_last;
    if (tid == 0) {
        __threadfence();
        int old = atomicAdd(&g_done, 1);
        s_last = (old == 2 * NACT - 1) ? 1 : 0;
        if (s_last) g_done = 0;
    }
    __syncthreads();
    if (!s_last) return;
    __threadfence();

    __shared__ float sl[NACT];
    if (tid < 32) {
        const int lane = tid;
        float l0 = g_part[0][lane]      + g_part[1][lane]      + hb[lane];
        float l1 = g_part[0][lane + 32] + g_part[1][lane + 32] + hb[lane + 32];
        sl[lane] = l0;
        sl[lane + 32] = l1;

        uint32_t kk0, kk1;
        threefry2x32(0u, 42u, 0u, (uint32_t)t, kk0, kk1);
        uint32_t a0, a1, b0, b1;
        threefry2x32(kk0, kk1, 0u, (uint32_t)lane,        a0, a1);
        threefry2x32(kk0, kk1, 0u, (uint32_t)(lane + 32), b0, b1);
        float u0 = jax_uniform(a0 ^ a1);
        float u1 = jax_uniform(b0 ^ b1);
        float gum0 = -logf(-logf(u0));
        float gum1 = -logf(-logf(u1));

        float v0 = l0 + gum0;
        float v1 = l1 + gum1;

        float bestv; int besti;
        if (v1 > v0) { bestv = v1; besti = lane + 32; }
        else         { bestv = v0; besti = lane; }
#pragma unroll
        for (int o = 16; o; o >>= 1) {
            float ov = __shfl_xor_sync(0xffffffffu, bestv, o);
            int   oi = __shfl_xor_sync(0xffffffffu, besti, o);
            if (ov > bestv || (ov == bestv && oi < besti)) { bestv = ov; besti = oi; }
        }
        float m = fmaxf(l0, l1);
#pragma unroll
        for (int o = 16; o; o >>= 1) m = fmaxf(m, __shfl_xor_sync(0xffffffffu, m, o));
        float se = expf(l0 - m) + expf(l1 - m);
#pragma unroll
        for (int o = 16; o; o >>= 1) se += __shfl_xor_sync(0xffffffffu, se, o);

        if (lane == 0) {
            float logp = (sl[besti] - m) - logf(se);
            float news = g_logp_sum + logp;
            g_logp_sum = news;
            g_action   = besti;
            out[t] = (float)besti;
            if (t == STEPS - 1 && out_size > STEPS) out[STEPS] = news;
        }
    }
    __syncthreads();
    int a = g_action;
    const float* src = action_emb + (size_t)a * H;
    for (int k = tid; k < H; k += 256) g_x[k] = src[k];
}

// ---------------- launch ----------------
extern "C" void kernel_launch(void* const* d_in, const int* in_sizes, int n_in,
                              void* d_out, int out_size) {
    const float* start_token = (const float*)d_in[0];
    const float* action_emb  = (const float*)d_in[1];
    const float* w_ih        = (const float*)d_in[2];
    const float* w_hh        = (const float*)d_in[3];
    const float* b_ih        = (const float*)d_in[4];
    const float* b_hh        = (const float*)d_in[5];
    const float* head_w      = (const float*)d_in[6];
    const float* head_b      = (const float*)d_in[7];
    float* out = (float*)d_out;

    convert_kernel<<<4096, 256>>>(w_ih, w_hh);
    init_kernel<<<(H + 255) / 256, 256>>>(start_token);

    for (int t = 0; t < STEPS; t++) {
        for (int l = 0; l < NLAYERS; l++) {
            cell_kernel<<<H, 256>>>(b_ih + (size_t)l * 4 * H,
                                    b_hh + (size_t)l * 4 * H,
                                    l, t);
        }
        head_sample_kernel<<<2 * NACT, 256>>>(head_w + (size_t)t * NACT * H,
                                              head_b + (size_t)t * NACT,
                                              action_emb, t, out, out_size);
    }
}